// round 14
// baseline (speedup 1.0000x reference)
#include <cuda_runtime.h>
#include <cuda_fp16.h>
#include <cstdint>

#define ITEM_NUM 100000
#define DIM 64
#define BS 256
#define NC 5

#define UPC 16                 // users per chunk
#define CHUNKS (BS / UPC)      // 16
#define CGC 4                  // chunks per CTA
#define NBLK (NC * 2)          // 10 n-tiles (8 cols) per chunk
#define M_TILE 128
#define THREADS 128
#define NTILES ((ITEM_NUM + M_TILE - 1) / M_TILE)   // 782
#define LOG2E 1.4426950408889634f

// A operand pre-packed in mma fragment order, fp16: [tile][tid][32 u32(half2)] = 12.8 MB.
__device__ uint32_t g_Af[(size_t)NTILES * THREADS * 32];
// B operand pre-packed per n-tile as [half-block][lane][8 f16]: 160 KB.
__device__ __half g_Bf[CHUNKS * NBLK * 32 * 16];

// ---------------- precompute A fragments (fp16, 2 warps per mt-half) ----------------
__global__ void precompute_Af(const float* __restrict__ item_table) {
    const int bi   = blockIdx.x;
    const int tid2 = threadIdx.x & 127;
    const int mt   = threadIdx.x >> 7;     // 0..1
    const int w = tid2 >> 5, t = tid2 & 31;
    const int qr = t >> 2, qc = t & 3;

    const int r0 = bi * M_TILE + w * 32 + mt * 16 + qr;
    const int r1 = r0 + 8;

    uint32_t frag[16];
    #pragma unroll
    for (int s = 0; s < 4; s++) {
        int k0 = s * 16 + qc * 2;
        float2 x0 = make_float2(0.f, 0.f), x1 = x0, x2 = x0, x3 = x0;
        if (r0 < ITEM_NUM) {
            x0 = *(const float2*)(item_table + (size_t)r0 * DIM + k0);
            x2 = *(const float2*)(item_table + (size_t)r0 * DIM + k0 + 8);
        }
        if (r1 < ITEM_NUM) {
            x1 = *(const float2*)(item_table + (size_t)r1 * DIM + k0);
            x3 = *(const float2*)(item_table + (size_t)r1 * DIM + k0 + 8);
        }
        __half2 h0 = __float22half2_rn(x0);
        __half2 h1 = __float22half2_rn(x1);
        __half2 h2 = __float22half2_rn(x2);
        __half2 h3 = __float22half2_rn(x3);
        frag[s * 4 + 0] = *(uint32_t*)&h0;
        frag[s * 4 + 1] = *(uint32_t*)&h1;
        frag[s * 4 + 2] = *(uint32_t*)&h2;
        frag[s * 4 + 3] = *(uint32_t*)&h3;
    }
    uint4* dst = (uint4*)(g_Af + ((size_t)bi * THREADS + tid2) * 32 + mt * 16);
    #pragma unroll
    for (int i = 0; i < 4; i++) dst[i] = ((uint4*)frag)[i];
}

// ---------------- precompute B fragments ----------------
// B[n-row = c*16 + uu][k] = user_emb[k] * W[c][k] * log2(e); within-lane slot
// order: k = s*16 + h*8 + (t%4)*2 + e; slot>>3 selects the 512B half-block.
__global__ void precompute_Bf(const void* __restrict__ batch_user,
                              const float* __restrict__ user_table,
                              const float* __restrict__ cls_w) {
    const int bi  = blockIdx.x;        // 0..159 = chunk*NBLK + nblk
    const int tid = threadIdx.x;       // 0..511
    const int t    = tid >> 4;         // lane 0..31
    const int slot = tid & 15;
    const int chunk = bi / NBLK;
    const int nblk  = bi % NBLK;

    const int cc = nblk >> 1, g = nblk & 1;
    const int uu = g * 8 + (t >> 2);   // n within tile -> user
    const int s = slot >> 2, h = (slot >> 1) & 1, e = slot & 1;
    const int k = s * 16 + h * 8 + (t & 3) * 2 + e;

    const int uslot = chunk * UPC + uu;
    const unsigned* q = (const unsigned*)batch_user;
    bool is64 = ((q[1] | q[3] | q[5] | q[7]) == 0u);
    long long uid = is64 ? ((const long long*)batch_user)[uslot]
                         : (long long)((const int*)batch_user)[uslot];

    g_Bf[(size_t)bi * 512 + (slot >> 3) * 256 + t * 8 + (slot & 7)] =
        __float2half(user_table[uid * DIM + k] * cls_w[cc * DIM + k] * LOG2E);
}

// f16-accumulator HMMA: d0 = rows qr (cols 2qc,2qc+1 packed), d1 = rows qr+8.
__device__ __forceinline__ void mma16816h(uint32_t& d0, uint32_t& d1,
                                          const uint32_t* a,
                                          uint32_t b0, uint32_t b1) {
    asm volatile(
        "mma.sync.aligned.m16n8k16.row.col.f16.f16.f16.f16 "
        "{%0,%1}, {%2,%3,%4,%5}, {%6,%7}, {%0,%1};"
        : "+r"(d0), "+r"(d1)
        : "r"(a[0]), "r"(a[1]), "r"(a[2]), "r"(a[3]), "r"(b0), "r"(b1));
}
__device__ __forceinline__ float ex2(float x) {
    float y; asm("ex2.approx.ftz.f32 %0, %1;" : "=f"(y) : "f"(x)); return y;
}
__device__ __forceinline__ float rcpf(float x) {
    float y; asm("rcp.approx.ftz.f32 %0, %1;" : "=f"(y) : "f"(x)); return y;
}

// ---------------- main kernel: fp16 MMA, no smem, no barriers ----------------
__global__ __launch_bounds__(THREADS, 6) void score_kernel(
    const float* __restrict__ cls_b,
    const float* __restrict__ values,
    float* __restrict__ out)
{
    const int tid = threadIdx.x;
    const int w   = tid >> 5;
    const int t   = tid & 31;
    const int qr  = t >> 2;
    const int qc  = t & 3;
    const int cg  = blockIdx.x;            // chunk-group 0..3
    const int bi  = blockIdx.y;            // item tile
    const int i0  = bi * M_TILE;

    // ---- A fragments: 8 coalesced LDG.128 from the fp16 fragment table ----
    uint32_t afr[2][4][4];
    {
        const uint4* ap = (const uint4*)(g_Af + ((size_t)bi * THREADS + tid) * 32);
        #pragma unroll
        for (int i = 0; i < 8; i++) ((uint4*)afr)[i] = __ldg(ap + i);
    }

    // ---- softmax constants; bias*log2e folded into accumulator init ----
    float v0  = __ldg(values);
    float wc[NC - 1];
    #pragma unroll
    for (int c = 1; c < NC; c++) wc[c - 1] = __ldg(values + c) - v0;
    uint32_t binit[NC];
    #pragma unroll
    for (int c = 0; c < NC; c++) {
        __half2 h = __float2half2_rn(__ldg(cls_b + c) * LOG2E);
        binit[c] = *(uint32_t*)&h;
    }

    // ---- per-thread output byte offsets (32-bit; output < 4GB) ----
    char* const outc = (char*)out;
    uint32_t ooff[2][2];
    bool valid[2][2];
    #pragma unroll
    for (int mt = 0; mt < 2; mt++)
        #pragma unroll
        for (int rh = 0; rh < 2; rh++) {
            int gi = i0 + w * 32 + mt * 16 + rh * 8 + qr;
            valid[mt][rh] = (gi < ITEM_NUM);
            ooff[mt][rh] = (uint32_t)((((cg * CGC * UPC) + qc * 2) * ITEM_NUM + gi) * 4);
        }

    #pragma unroll
    for (int j = 0; j < CGC; j++) {
        const int chunk = cg * CGC + j;

        #pragma unroll
        for (int g = 0; g < 2; g++) {       // 8-user half of the chunk
            uint32_t acc[2][NC][2];         // f16x2: [mt][class][row-half]
            #pragma unroll
            for (int mt = 0; mt < 2; mt++)
                #pragma unroll
                for (int cc = 0; cc < NC; cc++) {
                    acc[mt][cc][0] = binit[cc];
                    acc[mt][cc][1] = binit[cc];
                }

            #pragma unroll
            for (int cc = 0; cc < NC; cc++) {
                const int nblk = 2 * cc + g;
                // [bi][halfblock][lane][8 f16]: both loads lane-contiguous 512B.
                const uint4* bb = (const uint4*)g_Bf
                                  + (size_t)(chunk * NBLK + nblk) * 64;
                uint4 q0 = __ldg(bb + t);
                uint4 q1 = __ldg(bb + 32 + t);
                #pragma unroll
                for (int mt = 0; mt < 2; mt++) {
                    mma16816h(acc[mt][cc][0], acc[mt][cc][1], afr[mt][0], q0.x, q0.y);
                    mma16816h(acc[mt][cc][0], acc[mt][cc][1], afr[mt][1], q0.z, q0.w);
                    mma16816h(acc[mt][cc][0], acc[mt][cc][1], afr[mt][2], q1.x, q1.y);
                    mma16816h(acc[mt][cc][0], acc[mt][cc][1], afr[mt][3], q1.z, q1.w);
                }
            }

            // ---- fused softmax-EV epilogue: HSUB2 pair-subtract, EX2 f32 ----
            #pragma unroll
            for (int mt = 0; mt < 2; mt++)
                #pragma unroll
                for (int rh = 0; rh < 2; rh++) {
                    if (valid[mt][rh]) {
                        __half2 l0 = *(__half2*)&acc[mt][0][rh];
                        float den0 = 1.f, s0 = 0.f, den1 = 1.f, s1 = 0.f;
                        #pragma unroll
                        for (int cc = 1; cc < NC; cc++) {
                            __half2 d2 = __hsub2(*(__half2*)&acc[mt][cc][rh], l0);
                            float e0 = ex2(__low2float(d2));
                            float e1 = ex2(__high2float(d2));
                            den0 += e0; s0 = fmaf(e0, wc[cc - 1], s0);
                            den1 += e1; s1 = fmaf(e1, wc[cc - 1], s1);
                        }
                        float r0f = fmaf(s0, rcpf(den0), v0);
                        float r1f = fmaf(s1, rcpf(den1), v0);
                        char* p0 = outc + ooff[mt][rh]
                                 + (uint32_t)((g * 8) * ITEM_NUM * 4);
                        *(float*)p0 = r0f;
                        *(float*)(p0 + (uint32_t)(ITEM_NUM * 4)) = r1f;
                    }
                }
        }

        if (j + 1 < CGC) {
            #pragma unroll
            for (int mt = 0; mt < 2; mt++)
                #pragma unroll
                for (int rh = 0; rh < 2; rh++)
                    ooff[mt][rh] += (uint32_t)(UPC * ITEM_NUM * 4);
        }
    }
}

extern "C" void kernel_launch(void* const* d_in, const int* in_sizes, int n_in,
                              void* d_out, int out_size) {
    const void*  batch_user = d_in[0];
    const float* user_table = (const float*)d_in[1];
    const float* item_table = (const float*)d_in[2];
    const float* cls_w      = (const float*)d_in[3];
    const float* cls_b      = (const float*)d_in[4];
    const float* values     = (const float*)d_in[5];
    float* out = (float*)d_out;

    precompute_Af<<<NTILES, 256>>>(item_table);
    precompute_Bf<<<CHUNKS * NBLK, 512>>>(batch_user, user_table, cls_w);

    dim3 grid(CHUNKS / CGC, NTILES);   // (4, 782)
    score_kernel<<<grid, THREADS>>>(cls_b, values, out);
}

// round 15
// speedup vs baseline: 1.1317x; 1.1317x over previous
#include <cuda_runtime.h>
#include <cuda_fp16.h>
#include <cstdint>

#define ITEM_NUM 100000
#define DIM 64
#define BS 256
#define NC 5

#define UPC 16                 // users per chunk
#define CHUNKS (BS / UPC)      // 16
#define CGC 8                  // chunks per CTA
#define NBLK (NC * 2)          // 10 n-tiles (8 cols) per chunk
#define M_TILE 128
#define THREADS 128
#define NTILES ((ITEM_NUM + M_TILE - 1) / M_TILE)   // 782
#define LOG2E 1.4426950408889634f

// B operand pre-packed per n-tile as [half-block][lane][8 f16] so each warp
// quad-load is lane-contiguous 512B (4 L1 wavefronts). 160 KB total.
__device__ __half g_Bf[CHUNKS * NBLK * 32 * 16];

// ---------------- precompute B fragments ----------------
// B[n-row = c*16 + uu][k] = user_emb[k] * W[c][k] * log2(e); within-lane slot
// order: k = s*16 + h*8 + (t%4)*2 + e; slot>>3 selects the 512B half-block.
__global__ void precompute_Bf(const void* __restrict__ batch_user,
                              const float* __restrict__ user_table,
                              const float* __restrict__ cls_w) {
    const int bi  = blockIdx.x;        // 0..159 = chunk*NBLK + nblk
    const int tid = threadIdx.x;       // 0..511
    const int t    = tid >> 4;         // lane 0..31
    const int slot = tid & 15;
    const int chunk = bi / NBLK;
    const int nblk  = bi % NBLK;

    const int cc = nblk >> 1, g = nblk & 1;
    const int uu = g * 8 + (t >> 2);   // n within tile -> user
    const int s = slot >> 2, h = (slot >> 1) & 1, e = slot & 1;
    const int k = s * 16 + h * 8 + (t & 3) * 2 + e;

    const int uslot = chunk * UPC + uu;
    const unsigned* q = (const unsigned*)batch_user;
    bool is64 = ((q[1] | q[3] | q[5] | q[7]) == 0u);
    long long uid = is64 ? ((const long long*)batch_user)[uslot]
                         : (long long)((const int*)batch_user)[uslot];

    // coalesced-friendly layout: [bi][slot>>3][lane][slot&7]
    g_Bf[(size_t)bi * 512 + (slot >> 3) * 256 + t * 8 + (slot & 7)] =
        __float2half(user_table[uid * DIM + k] * cls_w[cc * DIM + k] * LOG2E);
}

// f16-accumulator HMMA: d0 = rows qr (cols 2qc,2qc+1 packed), d1 = rows qr+8.
__device__ __forceinline__ void mma16816h(uint32_t& d0, uint32_t& d1,
                                          const uint32_t* a,
                                          uint32_t b0, uint32_t b1) {
    asm volatile(
        "mma.sync.aligned.m16n8k16.row.col.f16.f16.f16.f16 "
        "{%0,%1}, {%2,%3,%4,%5}, {%6,%7}, {%0,%1};"
        : "+r"(d0), "+r"(d1)
        : "r"(a[0]), "r"(a[1]), "r"(a[2]), "r"(a[3]), "r"(b0), "r"(b1));
}
__device__ __forceinline__ float ex2(float x) {
    float y; asm("ex2.approx.ftz.f32 %0, %1;" : "=f"(y) : "f"(x)); return y;
}
__device__ __forceinline__ float rcpf(float x) {
    float y; asm("rcp.approx.ftz.f32 %0, %1;" : "=f"(y) : "f"(x)); return y;
}

// ---------------- main kernel: fp16 MMA, no smem, no barriers ----------------
__global__ __launch_bounds__(THREADS, 6) void score_kernel(
    const float* __restrict__ item_table,
    const float* __restrict__ cls_b,
    const float* __restrict__ values,
    float* __restrict__ out)
{
    const int tid = threadIdx.x;
    const int w   = tid >> 5;
    const int t   = tid & 31;
    const int qr  = t >> 2;
    const int qc  = t & 3;
    const int cg  = blockIdx.x;            // chunk-group 0..1
    const int i0  = blockIdx.y * M_TILE;   // item tile base

    // ---- A fragments (items, fp16) once: 2 m-tiles x 4 k-steps x 4 regs ----
    uint32_t afr[2][4][4];
    #pragma unroll
    for (int mt = 0; mt < 2; mt++) {
        int r0 = i0 + w * 32 + mt * 16 + qr;
        int r1 = r0 + 8;
        #pragma unroll
        for (int s = 0; s < 4; s++) {
            int k0 = s * 16 + qc * 2;
            float2 x0 = make_float2(0.f, 0.f), x1 = x0, x2 = x0, x3 = x0;
            if (r0 < ITEM_NUM) {
                x0 = *(const float2*)(item_table + (size_t)r0 * DIM + k0);
                x2 = *(const float2*)(item_table + (size_t)r0 * DIM + k0 + 8);
            }
            if (r1 < ITEM_NUM) {
                x1 = *(const float2*)(item_table + (size_t)r1 * DIM + k0);
                x3 = *(const float2*)(item_table + (size_t)r1 * DIM + k0 + 8);
            }
            __half2 h0 = __float22half2_rn(x0);
            __half2 h1 = __float22half2_rn(x1);
            __half2 h2 = __float22half2_rn(x2);
            __half2 h3 = __float22half2_rn(x3);
            afr[mt][s][0] = *(uint32_t*)&h0;
            afr[mt][s][1] = *(uint32_t*)&h1;
            afr[mt][s][2] = *(uint32_t*)&h2;
            afr[mt][s][3] = *(uint32_t*)&h3;
        }
    }

    // ---- softmax constants; bias*log2e folded into accumulator init ----
    float v0  = __ldg(values);
    float wc[NC - 1];
    #pragma unroll
    for (int c = 1; c < NC; c++) wc[c - 1] = __ldg(values + c) - v0;
    uint32_t binit[NC];
    #pragma unroll
    for (int c = 0; c < NC; c++) {
        __half2 h = __float2half2_rn(__ldg(cls_b + c) * LOG2E);
        binit[c] = *(uint32_t*)&h;
    }

    // ---- per-thread output byte offsets (32-bit; output < 4GB) ----
    char* const outc = (char*)out;
    uint32_t ooff[2][2];
    bool valid[2][2];
    #pragma unroll
    for (int mt = 0; mt < 2; mt++)
        #pragma unroll
        for (int rh = 0; rh < 2; rh++) {
            int gi = i0 + w * 32 + mt * 16 + rh * 8 + qr;
            valid[mt][rh] = (gi < ITEM_NUM);
            ooff[mt][rh] = (uint32_t)((((cg * CGC * UPC) + qc * 2) * ITEM_NUM + gi) * 4);
        }

    #pragma unroll 1
    for (int j = 0; j < CGC; j++) {
        const int chunk = cg * CGC + j;

        #pragma unroll
        for (int g = 0; g < 2; g++) {       // 8-user half of the chunk
            uint32_t acc[2][NC][2];         // f16x2: [mt][class][row-half]
            #pragma unroll
            for (int mt = 0; mt < 2; mt++)
                #pragma unroll
                for (int cc = 0; cc < NC; cc++) {
                    acc[mt][cc][0] = binit[cc];
                    acc[mt][cc][1] = binit[cc];
                }

            #pragma unroll
            for (int cc = 0; cc < NC; cc++) {
                const int nblk = 2 * cc + g;
                // [bi][halfblock][lane][8 f16]: both loads lane-contiguous 512B.
                const uint4* bb = (const uint4*)g_Bf
                                  + (size_t)(chunk * NBLK + nblk) * 64;
                uint4 q0 = __ldg(bb + t);
                uint4 q1 = __ldg(bb + 32 + t);
                #pragma unroll
                for (int mt = 0; mt < 2; mt++) {
                    mma16816h(acc[mt][cc][0], acc[mt][cc][1], afr[mt][0], q0.x, q0.y);
                    mma16816h(acc[mt][cc][0], acc[mt][cc][1], afr[mt][1], q0.z, q0.w);
                    mma16816h(acc[mt][cc][0], acc[mt][cc][1], afr[mt][2], q1.x, q1.y);
                    mma16816h(acc[mt][cc][0], acc[mt][cc][1], afr[mt][3], q1.z, q1.w);
                }
            }

            // ---- fused softmax-EV epilogue: HSUB2 pair-subtract, EX2 f32 ----
            #pragma unroll
            for (int mt = 0; mt < 2; mt++)
                #pragma unroll
                for (int rh = 0; rh < 2; rh++) {
                    if (valid[mt][rh]) {
                        __half2 l0 = *(__half2*)&acc[mt][0][rh];
                        float den0 = 1.f, s0 = 0.f, den1 = 1.f, s1 = 0.f;
                        #pragma unroll
                        for (int cc = 1; cc < NC; cc++) {
                            __half2 d2 = __hsub2(*(__half2*)&acc[mt][cc][rh], l0);
                            float e0 = ex2(__low2float(d2));
                            float e1 = ex2(__high2float(d2));
                            den0 += e0; s0 = fmaf(e0, wc[cc - 1], s0);
                            den1 += e1; s1 = fmaf(e1, wc[cc - 1], s1);
                        }
                        float r0f = fmaf(s0, rcpf(den0), v0);
                        float r1f = fmaf(s1, rcpf(den1), v0);
                        char* p0 = outc + ooff[mt][rh]
                                 + (uint32_t)((g * 8) * ITEM_NUM * 4);
                        *(float*)p0 = r0f;
                        *(float*)(p0 + (uint32_t)(ITEM_NUM * 4)) = r1f;
                    }
                }
        }

        if (j + 1 < CGC) {
            #pragma unroll
            for (int mt = 0; mt < 2; mt++)
                #pragma unroll
                for (int rh = 0; rh < 2; rh++)
                    ooff[mt][rh] += (uint32_t)(UPC * ITEM_NUM * 4);
        }
    }
}

extern "C" void kernel_launch(void* const* d_in, const int* in_sizes, int n_in,
                              void* d_out, int out_size) {
    const void*  batch_user = d_in[0];
    const float* user_table = (const float*)d_in[1];
    const float* item_table = (const float*)d_in[2];
    const float* cls_w      = (const float*)d_in[3];
    const float* cls_b      = (const float*)d_in[4];
    const float* values     = (const float*)d_in[5];
    float* out = (float*)d_out;

    precompute_Bf<<<CHUNKS * NBLK, 512>>>(batch_user, user_table, cls_w);

    dim3 grid(CHUNKS / CGC, NTILES);   // (2, 782)
    score_kernel<<<grid, THREADS>>>(item_table, cls_b, values, out);
}